// round 6
// baseline (speedup 1.0000x reference)
#include <cuda_runtime.h>
#include <cuda_fp16.h>
#include <cstdint>

#define Bz 4
#define S 1024
#define D 768
#define H 12
#define DK 64
#define BH (Bz*H)

// ---------------- scratch (device globals) ----------------
__device__ float  g_A1r[Bz*S*D];            // pro1 rounded to tf32
__device__ float  g_A2r[Bz*S*D];            // pro2 rounded
__device__ float  g_W1r[D*D];               // W_Q rounded
__device__ float  g_W2r[D*D];               // W_K rounded
__device__ float  g_W3r[D*D];               // fc1 rounded
__device__ float  g_Q[Bz*S*D];
__device__ float  g_K[Bz*S*D];
__device__ float  g_QT[BH*DK*S];            // fp32 (tf32-rounded), scoresT B operand
__device__ __half g_QTh[BH*DK*S];           // fp16, ctx2 B operand
__device__ __half g_KTh[BH*DK*S];           // fp16, ctx1 B operand
__device__ float  g_KTf[BH*DK*S];           // fp32 K transpose (unused sink)
__device__ __half g_P [(size_t)BH*S*S];     // P[bh][t][s] = exp(score), 0 if masked
__device__ __half g_PT[(size_t)BH*S*S];     // P^T[bh][s][t]
__device__ float  g_ctx[2*Bz*S*D];          // ctx1 | ctx2 (tf32-rounded)
__device__ float  g_t[2*Bz*S*D];
__device__ float  g_cpr[BH*8*S];
__device__ float  g_cpc[BH*8*S];
__device__ float  g_rinv[BH*S];
__device__ float  g_cinv[BH*S];
__device__ int    g_mask_mode;

// ---------------- helpers ----------------
__device__ __forceinline__ unsigned tf32c(float x) {
    unsigned u; asm("cvt.rna.tf32.f32 %0, %1;" : "=r"(u) : "f"(x)); return u;
}
__device__ __forceinline__ void mma8(float c[4], const unsigned a[4], const unsigned b[2]) {
    asm volatile(
        "mma.sync.aligned.m16n8k8.row.col.f32.tf32.tf32.f32 "
        "{%0,%1,%2,%3},{%4,%5,%6,%7},{%8,%9},{%0,%1,%2,%3};\n"
        : "+f"(c[0]), "+f"(c[1]), "+f"(c[2]), "+f"(c[3])
        : "r"(a[0]), "r"(a[1]), "r"(a[2]), "r"(a[3]), "r"(b[0]), "r"(b[1]));
}
__device__ __forceinline__ void hmma16(float c[4], const unsigned a[4], const unsigned b[2]) {
    asm volatile(
        "mma.sync.aligned.m16n8k16.row.col.f32.f16.f16.f32 "
        "{%0,%1,%2,%3},{%4,%5,%6,%7},{%8,%9},{%0,%1,%2,%3};\n"
        : "+f"(c[0]), "+f"(c[1]), "+f"(c[2]), "+f"(c[3])
        : "r"(a[0]), "r"(a[1]), "r"(a[2]), "r"(a[3]), "r"(b[0]), "r"(b[1]));
}
__device__ __forceinline__ int kperm(int k) {
    return (k & ~7) + 2 * (k & 3) + ((k & 7) >> 2);
}
__device__ __forceinline__ unsigned smem_u32(const void* p) {
    unsigned a;
    asm("{ .reg .u64 t; cvta.to.shared.u64 t, %1; cvt.u32.u64 %0, t; }" : "=r"(a) : "l"(p));
    return a;
}
__device__ __forceinline__ void cp16(unsigned d, const void* s) {
    asm volatile("cp.async.cg.shared.global [%0], [%1], 16;\n" :: "r"(d), "l"(s));
}
__device__ __forceinline__ void cp_commit() { asm volatile("cp.async.commit_group;\n"); }
__device__ __forceinline__ void cp_wait1()  { asm volatile("cp.async.wait_group 1;\n" ::: "memory"); }
__device__ __forceinline__ void cp_wait0()  { asm volatile("cp.async.wait_group 0;\n" ::: "memory"); }

// ---------------- mask dtype sniffer ----------------
__global__ void detect_mask_kernel(const unsigned int* __restrict__ w) {
    __shared__ int s01, sf;
    if (threadIdx.x == 0) { s01 = 1; sf = 1; }
    __syncthreads();
    int a01 = 1, af = 1;
    for (int i = threadIdx.x; i < 4096; i += 256) {
        unsigned v = w[i];
        if (v != 0u && v != 1u) a01 = 0;
        if (v != 0u && v != 0x3F800000u) af = 0;
    }
    if (!a01) atomicAnd(&s01, 0);
    if (!af)  atomicAnd(&sf, 0);
    __syncthreads();
    if (threadIdx.x == 0) g_mask_mode = s01 ? 0 : (sf ? 2 : 1);
}

// ---------------- round array to tf32 (rna) ----------------
__global__ void prep_round_kernel(const float* __restrict__ x, float* __restrict__ y, int n4) {
    int i = blockIdx.x * 256 + threadIdx.x;
    if (i < n4) {
        float4 v = ((const float4*)x)[i];
        uint4 u; u.x = tf32c(v.x); u.y = tf32c(v.y); u.z = tf32c(v.z); u.w = tf32c(v.w);
        ((uint4*)y)[i] = u;
    }
}

// ---------------- tf32 GEMM 128x128x32, cp.async 2-stage (inputs pre-rounded) ----------------
#define MM_STAGE 8832   // words: A 128*36 + B 32*132
__global__ void __launch_bounds__(256) mm128_kernel(const float* __restrict__ A,
                                                    const float* __restrict__ B,
                                                    float* __restrict__ C, int round_out) {
    extern __shared__ unsigned dsm[];
    const int m0 = blockIdx.y * 128, n0 = blockIdx.x * 128;
    const int tid = threadIdx.x, lane = tid & 31, w = tid >> 5;
    const int g = lane >> 2, tq = lane & 3;
    const int mw = (w & 1) * 64, nw = (w >> 1) * 32;
    const int arow = tid >> 1, ac0 = (tid & 1) * 16;
    const int brow = tid >> 3, bc0 = (tid & 7) * 16;
    const unsigned sbase = smem_u32(dsm);
    const float* Ab = A + (size_t)(m0 + arow) * 768 + ac0;
    const float* Bb = B + (size_t)brow * 768 + n0 + bc0;
    const unsigned dA = sbase + (unsigned)(arow * 36 + ac0) * 4u;
    const unsigned dB = sbase + (unsigned)(4608 + kperm(brow) * 132 + bc0) * 4u;
    float c[16][4] = {};

    #pragma unroll
    for (int j = 0; j < 4; j++) cp16(dA + j * 16, Ab + j * 4);
    #pragma unroll
    for (int j = 0; j < 4; j++) cp16(dB + j * 16, Bb + j * 4);
    cp_commit();

    int st = 0;
    for (int k0 = 0; k0 < 768; k0 += 32) {
        if (k0 + 32 < 768) {
            unsigned o = (unsigned)(st ^ 1) * (MM_STAGE * 4u);
            #pragma unroll
            for (int j = 0; j < 4; j++) cp16(dA + o + j * 16, Ab + k0 + 32 + j * 4);
            #pragma unroll
            for (int j = 0; j < 4; j++) cp16(dB + o + j * 16, Bb + (size_t)(k0 + 32) * 768 + j * 4);
            cp_commit();
            cp_wait1();
        } else {
            cp_wait0();
        }
        __syncthreads();
        const unsigned* As = dsm + st * MM_STAGE;
        const unsigned* Bs = As + 4608;
        #pragma unroll
        for (int ks = 0; ks < 4; ks++) {
            unsigned a[4][4], bf[4][2];
            #pragma unroll
            for (int i = 0; i < 4; i++) {
                int r = mw + 16 * i + g;
                const unsigned* pr = &As[r * 36 + ks * 8 + tq];
                a[i][0] = pr[0];      a[i][2] = pr[4];
                a[i][1] = pr[8 * 36]; a[i][3] = pr[8 * 36 + 4];
            }
            #pragma unroll
            for (int j = 0; j < 4; j++) {
                int col = nw + 8 * j + g;
                bf[j][0] = Bs[(ks * 8 + 2 * tq) * 132 + col];
                bf[j][1] = Bs[(ks * 8 + 2 * tq + 1) * 132 + col];
            }
            #pragma unroll
            for (int i = 0; i < 4; i++)
                #pragma unroll
                for (int j = 0; j < 4; j++) mma8(c[i * 4 + j], a[i], bf[j]);
        }
        st ^= 1;
        __syncthreads();
    }
    #pragma unroll
    for (int i = 0; i < 4; i++) {
        int r = m0 + mw + 16 * i + g;
        #pragma unroll
        for (int j = 0; j < 4; j++) {
            int col = n0 + nw + 8 * j + 2 * tq;
            float2 v0 = make_float2(c[i*4+j][0], c[i*4+j][1]);
            float2 v1 = make_float2(c[i*4+j][2], c[i*4+j][3]);
            if (round_out) {
                v0.x = __uint_as_float(tf32c(v0.x)); v0.y = __uint_as_float(tf32c(v0.y));
                v1.x = __uint_as_float(tf32c(v1.x)); v1.y = __uint_as_float(tf32c(v1.y));
            }
            *(float2*)(C + (size_t)r * 768 + col)       = v0;
            *(float2*)(C + (size_t)(r + 8) * 768 + col) = v1;
        }
    }
}

// ---------------- head transpose: X[b][s][h*64+d] -> XT fp32 + XTh fp16 ----------------
__global__ void tr_kernel(const float* __restrict__ X, float* __restrict__ XT,
                          __half* __restrict__ XTh) {
    __shared__ float tile[32][33];
    int bh = blockIdx.z, b = bh / H, h = bh % H;
    int s0 = blockIdx.x * 32, d0 = blockIdx.y * 32;
    int tx = threadIdx.x, ty = threadIdx.y;
    #pragma unroll
    for (int i = 0; i < 4; i++)
        tile[ty + 8 * i][tx] = X[(size_t)(b * S + s0 + ty + 8 * i) * D + h * DK + d0 + tx];
    __syncthreads();
    #pragma unroll
    for (int i = 0; i < 4; i++) {
        float v = tile[tx][ty + 8 * i];
        size_t idx = (size_t)(bh * DK + d0 + ty + 8 * i) * S + s0 + tx;
        XT[idx]  = v;
        XTh[idx] = __float2half_rn(v);
    }
}

// ---------------- scoresT: P, PT fp16 + partial sums (swizzled smem tile) ----------------
#define PSW(t, c) (((c) + 5 * (t)) & 63)
__global__ void __launch_bounds__(256) scoresT_kernel(const float* __restrict__ Kmat,
                                                      const float* __restrict__ QT,
                                                      const void* __restrict__ mask,
                                                      __half* __restrict__ P,
                                                      __half* __restrict__ PT,
                                                      float* __restrict__ cpr,
                                                      float* __restrict__ cpc) {
    __shared__ union SU {
        struct { unsigned As[128 * 36]; unsigned Bs[32 * 132]; } g;
        __half2 Ps[128 * 68];   // [t][unit], unit swizzled by PSW
    } su;
    unsigned* As = su.g.As;
    unsigned* Bs = su.g.Bs;
    const int bh = blockIdx.z, b = bh / H, h = bh % H;
    const int s0 = blockIdx.x * 128, t0 = blockIdx.y * 128;
    const float* Ag = Kmat + (size_t)(b * S + t0) * D + h * DK;
    const float* Bg = QT + (size_t)bh * DK * S + s0;
    const int tid = threadIdx.x, lane = tid & 31, w = tid >> 5;
    const int g = lane >> 2, tq = lane & 3;
    const int mw = (w & 1) * 64, nw = (w >> 1) * 32;
    float c[16][4] = {};
    #pragma unroll
    for (int k0 = 0; k0 < 64; k0 += 32) {
        {
            int kq = tid & 7, kc = kq * 4, bkp = (kq >> 1) * 8 + (kq & 1);
            #pragma unroll
            for (int it = 0; it < 4; it++) {
                int m = (tid >> 3) + it * 32;
                float4 v = *(const float4*)(Ag + (size_t)m * D + k0 + kc);
                unsigned* dst = &As[m * 36 + bkp];
                dst[0] = __float_as_uint(v.x); dst[2] = __float_as_uint(v.y);
                dst[4] = __float_as_uint(v.z); dst[6] = __float_as_uint(v.w);
            }
        }
        {
            #pragma unroll
            for (int it = 0; it < 4; it++) {
                int kr = (tid >> 5) + it * 8;
                int nc = lane * 4;
                float4 v = *(const float4*)(Bg + (size_t)(k0 + kr) * S + nc);
                uint4 u; u.x = __float_as_uint(v.x); u.y = __float_as_uint(v.y);
                u.z = __float_as_uint(v.z); u.w = __float_as_uint(v.w);
                *(uint4*)&Bs[kperm(kr) * 132 + nc] = u;
            }
        }
        __syncthreads();
        #pragma unroll
        for (int ks = 0; ks < 4; ks++) {
            unsigned a[4][4], bf[4][2];
            #pragma unroll
            for (int i = 0; i < 4; i++) {
                int r = mw + 16 * i + g;
                uint2 x = *(const uint2*)&As[r * 36 + ks * 8 + 2 * tq];
                uint2 y = *(const uint2*)&As[(r + 8) * 36 + ks * 8 + 2 * tq];
                a[i][0] = x.x; a[i][1] = y.x; a[i][2] = x.y; a[i][3] = y.y;
            }
            #pragma unroll
            for (int j = 0; j < 4; j++) {
                int col = nw + 8 * j + g;
                bf[j][0] = Bs[(ks * 8 + 2 * tq) * 132 + col];
                bf[j][1] = Bs[(ks * 8 + 2 * tq + 1) * 132 + col];
            }
            #pragma unroll
            for (int i = 0; i < 4; i++)
                #pragma unroll
                for (int j = 0; j < 4; j++) mma8(c[i * 4 + j], a[i], bf[j]);
        }
        __syncthreads();
    }
    // mask + exp -> swizzled smem tile
    const int mode = g_mask_mode;
    const int* m32 = (const int*)mask;
    const unsigned char* m8 = (const unsigned char*)mask;
    const float* mf = (const float*)mask;
    #pragma unroll
    for (int i = 0; i < 4; i++) {
        int tl = mw + 16 * i + g;
        int rA = t0 + tl;
        #pragma unroll
        for (int j = 0; j < 4; j++) {
            int sl = nw + 8 * j + 2 * tq;
            int cs = s0 + sl;
            float* cc = c[i * 4 + j];
            size_t iA = ((size_t)bh * S + rA) * S + cs;
            size_t iB = iA + (size_t)8 * S;
            bool k0m, k1m, k2m, k3m;
            if (mode == 0) {
                int2 qa = *(const int2*)(m32 + iA); int2 qb = *(const int2*)(m32 + iB);
                k0m = qa.x != 0; k1m = qa.y != 0; k2m = qb.x != 0; k3m = qb.y != 0;
            } else if (mode == 1) {
                uchar2 qa = *(const uchar2*)(m8 + iA); uchar2 qb = *(const uchar2*)(m8 + iB);
                k0m = qa.x != 0; k1m = qa.y != 0; k2m = qb.x != 0; k3m = qb.y != 0;
            } else {
                float2 qa = *(const float2*)(mf + iA); float2 qb = *(const float2*)(mf + iB);
                k0m = qa.x != 0.0f; k1m = qa.y != 0.0f; k2m = qb.x != 0.0f; k3m = qb.y != 0.0f;
            }
            float p0 = k0m ? 0.0f : __expf(0.125f * cc[0]);
            float p1 = k1m ? 0.0f : __expf(0.125f * cc[1]);
            float p2 = k2m ? 0.0f : __expf(0.125f * cc[2]);
            float p3 = k3m ? 0.0f : __expf(0.125f * cc[3]);
            int cu = sl >> 1;
            su.Ps[tl * 68 + PSW(tl, cu)]             = __floats2half2_rn(p0, p1);
            su.Ps[(tl + 8) * 68 + PSW(tl + 8, cu)]   = __floats2half2_rn(p2, p3);
        }
    }
    __syncthreads();
    // partial sums
    if (tid < 128) {
        // per-t sum over s (row is a permutation; read linearly)
        float rs = 0.f;
        const __half2* row = &su.Ps[tid * 68];
        #pragma unroll 16
        for (int j = 0; j < 64; j++) {
            float2 f = __half22float2(row[j]);
            rs += f.x + f.y;
        }
        cpc[((size_t)bh * 8 + blockIdx.x) * S + t0 + tid] = rs;
        // per-s sum over t
        int cu = tid >> 1, hh = tid & 1;
        float csum = 0.f;
        #pragma unroll 16
        for (int r = 0; r < 128; r++) {
            __half2 v = su.Ps[r * 68 + PSW(r, cu)];
            csum += __half2float(hh ? __high2half(v) : __low2half(v));
        }
        cpr[((size_t)bh * 8 + blockIdx.y) * S + s0 + tid] = csum;
    }
    __syncthreads();
    // write P[t][s]
    #pragma unroll
    for (int it = 0; it < 32; it++) {
        int t = it * 4 + (tid >> 6);
        int u = tid & 63;
        __half2 v = su.Ps[t * 68 + PSW(t, u)];
        *(__half2*)(P + ((size_t)bh * S + t0 + t) * S + s0 + 2 * u) = v;
    }
    // write PT[s][t]
    #pragma unroll
    for (int it = 0; it < 32; it++) {
        int s = it * 4 + (tid >> 6);
        int tp = tid & 63;
        int cu = s >> 1, hh = s & 1;
        __half2 va = su.Ps[(2 * tp) * 68 + PSW(2 * tp, cu)];
        __half2 vb = su.Ps[(2 * tp + 1) * 68 + PSW(2 * tp + 1, cu)];
        __half h0 = hh ? __high2half(va) : __low2half(va);
        __half h1 = hh ? __high2half(vb) : __low2half(vb);
        *(__half2*)(PT + ((size_t)bh * S + s0 + s) * S + t0 + 2 * tp) = __halves2half2(h0, h1);
    }
}

// ---------------- reduce partials -> rinv, cinv ----------------
__global__ void rcinv_kernel(const float* __restrict__ cpr, const float* __restrict__ cpc,
                             float* __restrict__ rinv, float* __restrict__ cinv) {
    int bh = blockIdx.y;
    int x = blockIdx.x * 256 + threadIdx.x;
    float sr = 0.f, sc = 0.f;
    #pragma unroll
    for (int j = 0; j < 8; j++) {
        sr += cpr[((size_t)bh * 8 + j) * S + x];
        sc += cpc[((size_t)bh * 8 + j) * S + x];
    }
    rinv[bh * S + x] = 1.0f / sr;
    cinv[bh * S + x] = 1.0f / sc;
}

// ---------------- ctx (fp16 HMMA, cp.async 2-stage) ----------------
// C[m][d] = round_tf32( minv[m] * sum_k A[m][k] * XT[d][k] )
#define CTX_STAGE 6400  // words: A 256*20 + B 64*20
__global__ void __launch_bounds__(256) ctxh_kernel(const __half* __restrict__ A,
                                                   const __half* __restrict__ XTh,
                                                   const float* __restrict__ minv,
                                                   float* __restrict__ C) {
    extern __shared__ unsigned dsm[];
    __shared__ float mv[256];
    const int bh = blockIdx.y, b = bh / H, h = bh % H;
    const int m0 = blockIdx.x * 256;
    const __half* Ag = A + ((size_t)bh * S + m0) * S;
    const __half* Bg = XTh + (size_t)bh * DK * S;
    const int tid = threadIdx.x, lane = tid & 31, w = tid >> 5;
    const int g = lane >> 2, tq = lane & 3;
    const int mw = (w >> 1) * 64, nw = (w & 1) * 32;
    mv[tid] = minv[bh * S + m0 + tid];
    const unsigned sbase = smem_u32(dsm);
    const __half* Ab = Ag + (size_t)tid * S;                       // row tid, 4 chunks
    const __half* Bb = Bg + (size_t)(tid >> 2) * S + (tid & 3) * 8; // row tid>>2, chunk tid&3
    const unsigned dA = sbase + (unsigned)(tid * 20) * 4u;
    const unsigned dB = sbase + (unsigned)(256 * 20 + (tid >> 2) * 20 + (tid & 3) * 4) * 4u;
    float c[16][4] = {};

    #pragma unroll
    for (int j = 0; j < 4; j++) cp16(dA + j * 16, Ab + j * 8);
    cp16(dB, Bb);
    cp_commit();

    int st = 0;
    for (int k0 = 0; k0 < S; k0 += 32) {
        if (k0 + 32 < S) {
            unsigned o = (unsigned)(st ^ 1) * (CTX_STAGE * 4u);
            #pragma unroll
            for (int j = 0; j < 4; j++) cp16(dA + o + j * 16, Ab + k0 + 32 + j * 8);
            cp16(dB + o, Bb + k0 + 32);
            cp_commit();
            cp_wait1();
        } else {
            cp_wait0();
        }
        __syncthreads();
        const unsigned* Ah = dsm + st * CTX_STAGE;
        const unsigned* Bh = Ah + 256 * 20;
        #pragma unroll
        for (int ks = 0; ks < 2; ks++) {
            unsigned a[4][4], bf[4][2];
            #pragma unroll
            for (int i = 0; i < 4; i++) {
                int r = mw + 16 * i + g;
                a[i][0] = Ah[r * 20 + 8 * ks + tq];
                a[i][1] = Ah[(r + 8) * 20 + 8 * ks + tq];
                a[i][2] = Ah[r * 20 + 8 * ks + tq + 4];
                a[i][3] = Ah[(r + 8) * 20 + 8 * ks + tq + 4];
            }
            #pragma unroll
            for (int j = 0; j < 4; j++) {
                int col = nw + 8 * j + g;
                bf[j][0] = Bh[col * 20 + 8 * ks + tq];
                bf[j][1] = Bh[col * 20 + 8 * ks + tq + 4];
            }
            #pragma unroll
            for (int i = 0; i < 4; i++)
                #pragma unroll
                for (int j = 0; j < 4; j++) hmma16(c[i * 4 + j], a[i], bf[j]);
        }
        st ^= 1;
        __syncthreads();
    }
    #pragma unroll
    for (int i = 0; i < 4; i++) {
        int rl = mw + 16 * i + g;
        float s0v = mv[rl], s1v = mv[rl + 8];
        #pragma unroll
        for (int j = 0; j < 4; j++) {
            int dcol = nw + 8 * j + 2 * tq;
            float* cc = c[i * 4 + j];
            size_t a0 = (size_t)(b * S + m0 + rl) * D + h * DK + dcol;
            float2 v0 = make_float2(__uint_as_float(tf32c(cc[0] * s0v)),
                                    __uint_as_float(tf32c(cc[1] * s0v)));
            float2 v1 = make_float2(__uint_as_float(tf32c(cc[2] * s1v)),
                                    __uint_as_float(tf32c(cc[3] * s1v)));
            *(float2*)(C + a0)                 = v0;
            *(float2*)(C + a0 + (size_t)8 * D) = v1;
        }
    }
}

// ---------------- batched LayerNorm over last dim (768) ----------------
__global__ void ln_kernel(const float* __restrict__ x,
                          const float* __restrict__ g1, const float* __restrict__ b1,
                          const float* __restrict__ g2, const float* __restrict__ b2,
                          float* __restrict__ out) {
    int row = blockIdx.x, tid = threadIdx.x;
    const float* gg = (row < Bz * S) ? g1 : g2;
    const float* bb = (row < Bz * S) ? b1 : b2;
    const float* xr = x + (size_t)row * D;
    float v0 = xr[tid], v1 = xr[tid + 256], v2 = xr[tid + 512];
    float s = v0 + v1 + v2;
    __shared__ float red[8];
    #pragma unroll
    for (int o = 16; o; o >>= 1) s += __shfl_xor_sync(0xffffffffu, s, o);
    if ((tid & 31) == 0) red[tid >> 5] = s;
    __syncthreads();
    float tot = 0.f;
    #pragma unroll
    for (int i = 0; i < 8; i++) tot += red[i];
    float mu = tot * (1.0f / 768.0f);
    float d0 = v0 - mu, d1 = v1 - mu, d2 = v2 - mu;
    float q = d0 * d0 + d1 * d1 + d2 * d2;
    #pragma unroll
    for (int o = 16; o; o >>= 1) q += __shfl_xor_sync(0xffffffffu, q, o);
    __syncthreads();
    if ((tid & 31) == 0) red[tid >> 5] = q;
    __syncthreads();
    float var = 0.f;
    #pragma unroll
    for (int i = 0; i < 8; i++) var += red[i];
    var *= (1.0f / 768.0f);
    float rs = rsqrtf(var + 1e-5f);
    float* orow = out + (size_t)row * D;
    orow[tid]       = d0 * rs * gg[tid]       + bb[tid];
    orow[tid + 256] = d1 * rs * gg[tid + 256] + bb[tid + 256];
    orow[tid + 512] = d2 * rs * gg[tid + 512] + bb[tid + 512];
}

// ---------------- launch ----------------
extern "C" void kernel_launch(void* const* d_in, const int* in_sizes, int n_in,
                              void* d_out, int out_size) {
    const float* pro1 = (const float*)d_in[0];
    const float* pro2 = (const float*)d_in[1];
    const void*  mask = d_in[2];
    const float* W_Q  = (const float*)d_in[3];
    const float* W_K  = (const float*)d_in[4];
    const float* fc1  = (const float*)d_in[5];
    const float* g1   = (const float*)d_in[6];
    const float* b1   = (const float*)d_in[7];
    const float* g2   = (const float*)d_in[8];
    const float* b2   = (const float*)d_in[9];
    float* out = (float*)d_out;

    float *A1r, *A2r, *W1r, *W2r, *W3r, *Qp, *Kp, *QTp, *KTf, *CX, *Tp, *CPR, *CPC, *RI, *CI;
    __half *QTh, *KTh, *Pp, *PTp;
    cudaGetSymbolAddress((void**)&A1r, g_A1r);
    cudaGetSymbolAddress((void**)&A2r, g_A2r);
    cudaGetSymbolAddress((void**)&W1r, g_W1r);
    cudaGetSymbolAddress((void**)&W2r, g_W2r);
    cudaGetSymbolAddress((void**)&W3r, g_W3r);
    cudaGetSymbolAddress((void**)&Qp, g_Q);
    cudaGetSymbolAddress((void**)&Kp, g_K);
    cudaGetSymbolAddress((void**)&QTp, g_QT);
    cudaGetSymbolAddress((void**)&QTh, g_QTh);
    cudaGetSymbolAddress((void**)&KTh, g_KTh);
    cudaGetSymbolAddress((void**)&KTf, g_KTf);
    cudaGetSymbolAddress((void**)&Pp, g_P);
    cudaGetSymbolAddress((void**)&PTp, g_PT);
    cudaGetSymbolAddress((void**)&CX, g_ctx);
    cudaGetSymbolAddress((void**)&Tp, g_t);
    cudaGetSymbolAddress((void**)&CPR, g_cpr);
    cudaGetSymbolAddress((void**)&CPC, g_cpc);
    cudaGetSymbolAddress((void**)&RI, g_rinv);
    cudaGetSymbolAddress((void**)&CI, g_cinv);

    cudaFuncSetAttribute(mm128_kernel, cudaFuncAttributeMaxDynamicSharedMemorySize, MM_STAGE * 8);
    cudaFuncSetAttribute(ctxh_kernel, cudaFuncAttributeMaxDynamicSharedMemorySize, CTX_STAGE * 8);

    detect_mask_kernel<<<1, 256>>>((const unsigned int*)mask);

    // pre-round GEMM inputs to tf32
    prep_round_kernel<<<3072, 256>>>(pro1, A1r, Bz * S * D / 4);
    prep_round_kernel<<<3072, 256>>>(pro2, A2r, Bz * S * D / 4);
    prep_round_kernel<<<576, 256>>>(W_Q, W1r, D * D / 4);
    prep_round_kernel<<<576, 256>>>(W_K, W2r, D * D / 4);
    prep_round_kernel<<<576, 256>>>(fc1, W3r, D * D / 4);

    dim3 gProj(6, 32);
    mm128_kernel<<<gProj, 256, MM_STAGE * 8>>>(A1r, W1r, Qp, 1);
    mm128_kernel<<<gProj, 256, MM_STAGE * 8>>>(A2r, W2r, Kp, 1);

    tr_kernel<<<dim3(32, 2, BH), dim3(32, 8)>>>(Qp, QTp, QTh);
    tr_kernel<<<dim3(32, 2, BH), dim3(32, 8)>>>(Kp, KTf, KTh);

    scoresT_kernel<<<dim3(8, 8, BH), 256>>>(Kp, QTp, mask, Pp, PTp, CPR, CPC);

    rcinv_kernel<<<dim3(4, BH), 256>>>(CPR, CPC, RI, CI);

    ctxh_kernel<<<dim3(4, BH), 256, CTX_STAGE * 8>>>(PTp, KTh, RI, CX);                      // ctx1
    ctxh_kernel<<<dim3(4, BH), 256, CTX_STAGE * 8>>>(Pp, QTh, CI, CX + (size_t)Bz * S * D);  // ctx2

    mm128_kernel<<<dim3(6, 64), 256, MM_STAGE * 8>>>(CX, W3r, Tp, 0);

    ln_kernel<<<2 * Bz * S, 256>>>(Tp, g1, b1, g2, b2, out);
}

// round 7
// speedup vs baseline: 1.0155x; 1.0155x over previous
#include <cuda_runtime.h>
#include <cuda_fp16.h>
#include <cstdint>

#define Bz 4
#define S 1024
#define D 768
#define H 12
#define DK 64
#define BH (Bz*H)

// ---------------- scratch (device globals) ----------------
__device__ float  g_Q[Bz*S*D];              // tf32-rounded Q projection
__device__ float  g_K[Bz*S*D];              // tf32-rounded K projection
__device__ float  g_QT[BH*DK*S];            // fp32 (rounded), scoresT B operand
__device__ __half g_QTh[BH*DK*S];           // fp16, ctx2 B operand
__device__ __half g_KTh[BH*DK*S];           // fp16, ctx1 B operand
__device__ float  g_KTf[BH*DK*S];           // fp32 K transpose (sink)
__device__ __half g_P [(size_t)BH*S*S];     // P[bh][t][s] = exp(score), 0 if masked
__device__ __half g_PT[(size_t)BH*S*S];     // P^T[bh][s][t]
__device__ float  g_ctx[2*Bz*S*D];          // ctx1 | ctx2
__device__ float  g_t[2*Bz*S*D];
__device__ float  g_cpr[BH*8*S];
__device__ float  g_cpc[BH*8*S];
__device__ float  g_rinv[BH*S];
__device__ float  g_cinv[BH*S];
__device__ int    g_mask_mode;

// ---------------- helpers ----------------
__device__ __forceinline__ unsigned tf32c(float x) {
    unsigned u; asm("cvt.rna.tf32.f32 %0, %1;" : "=r"(u) : "f"(x)); return u;
}
__device__ __forceinline__ void mma8(float c[4], const unsigned a[4], const unsigned b[2]) {
    asm volatile(
        "mma.sync.aligned.m16n8k8.row.col.f32.tf32.tf32.f32 "
        "{%0,%1,%2,%3},{%4,%5,%6,%7},{%8,%9},{%0,%1,%2,%3};\n"
        : "+f"(c[0]), "+f"(c[1]), "+f"(c[2]), "+f"(c[3])
        : "r"(a[0]), "r"(a[1]), "r"(a[2]), "r"(a[3]), "r"(b[0]), "r"(b[1]));
}
__device__ __forceinline__ void hmma16(float c[4], const unsigned a[4], const unsigned b[2]) {
    asm volatile(
        "mma.sync.aligned.m16n8k16.row.col.f32.f16.f16.f32 "
        "{%0,%1,%2,%3},{%4,%5,%6,%7},{%8,%9},{%0,%1,%2,%3};\n"
        : "+f"(c[0]), "+f"(c[1]), "+f"(c[2]), "+f"(c[3])
        : "r"(a[0]), "r"(a[1]), "r"(a[2]), "r"(a[3]), "r"(b[0]), "r"(b[1]));
}
__device__ __forceinline__ int kperm(int k) {
    return (k & ~7) + 2 * (k & 3) + ((k & 7) >> 2);
}

// ---------------- mask dtype sniffer ----------------
__global__ void detect_mask_kernel(const unsigned int* __restrict__ w) {
    __shared__ int s01, sf;
    if (threadIdx.x == 0) { s01 = 1; sf = 1; }
    __syncthreads();
    int a01 = 1, af = 1;
    for (int i = threadIdx.x; i < 4096; i += 256) {
        unsigned v = w[i];
        if (v != 0u && v != 1u) a01 = 0;
        if (v != 0u && v != 0x3F800000u) af = 0;
    }
    if (!a01) atomicAnd(&s01, 0);
    if (!af)  atomicAnd(&sf, 0);
    __syncthreads();
    if (threadIdx.x == 0) g_mask_mode = s01 ? 0 : (sf ? 2 : 1);
}

// ---------------- tf32 GEMM 128x64x32 tiles, 8 warps (4m x 2n), 16 acc/thread ----------------
// C[M x 768] = A[M x 768] @ B[768 x 768]; raw fp32 inputs, cvt on load.
__global__ void __launch_bounds__(256) mm128_kernel(const float* __restrict__ A,
                                                    const float* __restrict__ B,
                                                    float* __restrict__ C, int round_out) {
    __shared__ unsigned As[128 * 36];
    __shared__ unsigned Bs[32 * 68];
    const int m0 = blockIdx.y * 128, n0 = blockIdx.x * 64;
    const int tid = threadIdx.x, lane = tid & 31, w = tid >> 5;
    const int g = lane >> 2, tq = lane & 3;
    const int mw = (w & 3) * 32, nw = (w >> 2) * 32;
    float c[8][4] = {};
    for (int k0 = 0; k0 < 768; k0 += 32) {
        {   // A tile: 128x32
            int kq = tid & 7, kc = kq * 4, bkp = (kq >> 1) * 8 + (kq & 1);
            #pragma unroll
            for (int it = 0; it < 4; it++) {
                int m = (tid >> 3) + it * 32;
                float4 v = *(const float4*)(A + (size_t)(m0 + m) * 768 + k0 + kc);
                unsigned* dst = &As[m * 36 + bkp];
                dst[0] = tf32c(v.x); dst[2] = tf32c(v.y); dst[4] = tf32c(v.z); dst[6] = tf32c(v.w);
            }
        }
        {   // B tile: 32x64
            int kr = tid >> 3, nc = (tid & 7) * 8;
            const float* src = B + (size_t)(k0 + kr) * 768 + n0 + nc;
            float4 v0 = *(const float4*)src;
            float4 v1 = *(const float4*)(src + 4);
            unsigned* dst = &Bs[kperm(kr) * 68 + nc];
            uint4 u0; u0.x = tf32c(v0.x); u0.y = tf32c(v0.y); u0.z = tf32c(v0.z); u0.w = tf32c(v0.w);
            uint4 u1; u1.x = tf32c(v1.x); u1.y = tf32c(v1.y); u1.z = tf32c(v1.z); u1.w = tf32c(v1.w);
            *(uint4*)dst = u0;
            *(uint4*)(dst + 4) = u1;
        }
        __syncthreads();
        #pragma unroll
        for (int ks = 0; ks < 4; ks++) {
            unsigned a[2][4], bf[4][2];
            #pragma unroll
            for (int i = 0; i < 2; i++) {
                int r = mw + 16 * i + g;
                uint2 x = *(const uint2*)&As[r * 36 + ks * 8 + 2 * tq];
                uint2 y = *(const uint2*)&As[(r + 8) * 36 + ks * 8 + 2 * tq];
                a[i][0] = x.x; a[i][1] = y.x; a[i][2] = x.y; a[i][3] = y.y;
            }
            #pragma unroll
            for (int j = 0; j < 4; j++) {
                int col = nw + 8 * j + g;
                bf[j][0] = Bs[(ks * 8 + 2 * tq) * 68 + col];
                bf[j][1] = Bs[(ks * 8 + 2 * tq + 1) * 68 + col];
            }
            #pragma unroll
            for (int i = 0; i < 2; i++)
                #pragma unroll
                for (int j = 0; j < 4; j++) mma8(c[i * 4 + j], a[i], bf[j]);
        }
        __syncthreads();
    }
    #pragma unroll
    for (int i = 0; i < 2; i++) {
        int r = m0 + mw + 16 * i + g;
        #pragma unroll
        for (int j = 0; j < 4; j++) {
            int col = n0 + nw + 8 * j + 2 * tq;
            float2 v0 = make_float2(c[i*4+j][0], c[i*4+j][1]);
            float2 v1 = make_float2(c[i*4+j][2], c[i*4+j][3]);
            if (round_out) {
                v0.x = __uint_as_float(tf32c(v0.x)); v0.y = __uint_as_float(tf32c(v0.y));
                v1.x = __uint_as_float(tf32c(v1.x)); v1.y = __uint_as_float(tf32c(v1.y));
            }
            *(float2*)(C + (size_t)r * 768 + col)       = v0;
            *(float2*)(C + (size_t)(r + 8) * 768 + col) = v1;
        }
    }
}

// ---------------- head transpose: X[b][s][h*64+d] -> XT fp32 + XTh fp16 ----------------
__global__ void tr_kernel(const float* __restrict__ X, float* __restrict__ XT,
                          __half* __restrict__ XTh) {
    __shared__ float tile[32][33];
    int bh = blockIdx.z, b = bh / H, h = bh % H;
    int s0 = blockIdx.x * 32, d0 = blockIdx.y * 32;
    int tx = threadIdx.x, ty = threadIdx.y;
    #pragma unroll
    for (int i = 0; i < 4; i++)
        tile[ty + 8 * i][tx] = X[(size_t)(b * S + s0 + ty + 8 * i) * D + h * DK + d0 + tx];
    __syncthreads();
    #pragma unroll
    for (int i = 0; i < 4; i++) {
        float v = tile[tx][ty + 8 * i];
        size_t idx = (size_t)(bh * DK + d0 + ty + 8 * i) * S + s0 + tx;
        XT[idx]  = v;
        XTh[idx] = __float2half_rn(v);
    }
}

// ---------------- scoresT: P, PT fp16 + partial sums (inputs pre-rounded; no cvt) ----------------
#define PSW(t, c) (((c) + 5 * (t)) & 63)
__global__ void __launch_bounds__(256) scoresT_kernel(const float* __restrict__ Kmat,
                                                      const float* __restrict__ QT,
                                                      const void* __restrict__ mask,
                                                      __half* __restrict__ P,
                                                      __half* __restrict__ PT,
                                                      float* __restrict__ cpr,
                                                      float* __restrict__ cpc) {
    __shared__ union SU {
        struct { unsigned As[128 * 36]; unsigned Bs[32 * 132]; } g;
        __half2 Ps[128 * 68];
    } su;
    unsigned* As = su.g.As;
    unsigned* Bs = su.g.Bs;
    const int bh = blockIdx.z, b = bh / H, h = bh % H;
    const int s0 = blockIdx.x * 128, t0 = blockIdx.y * 128;
    const float* Ag = Kmat + (size_t)(b * S + t0) * D + h * DK;
    const float* Bg = QT + (size_t)bh * DK * S + s0;
    const int tid = threadIdx.x, lane = tid & 31, w = tid >> 5;
    const int g = lane >> 2, tq = lane & 3;
    const int mw = (w & 1) * 64, nw = (w >> 1) * 32;
    float c[16][4] = {};
    #pragma unroll
    for (int k0 = 0; k0 < 64; k0 += 32) {
        {
            int kq = tid & 7, kc = kq * 4, bkp = (kq >> 1) * 8 + (kq & 1);
            #pragma unroll
            for (int it = 0; it < 4; it++) {
                int m = (tid >> 3) + it * 32;
                float4 v = *(const float4*)(Ag + (size_t)m * D + k0 + kc);
                unsigned* dst = &As[m * 36 + bkp];
                dst[0] = __float_as_uint(v.x); dst[2] = __float_as_uint(v.y);
                dst[4] = __float_as_uint(v.z); dst[6] = __float_as_uint(v.w);
            }
        }
        {
            #pragma unroll
            for (int it = 0; it < 4; it++) {
                int kr = (tid >> 5) + it * 8;
                int nc = lane * 4;
                float4 v = *(const float4*)(Bg + (size_t)(k0 + kr) * S + nc);
                uint4 u; u.x = __float_as_uint(v.x); u.y = __float_as_uint(v.y);
                u.z = __float_as_uint(v.z); u.w = __float_as_uint(v.w);
                *(uint4*)&Bs[kperm(kr) * 132 + nc] = u;
            }
        }
        __syncthreads();
        #pragma unroll
        for (int ks = 0; ks < 4; ks++) {
            unsigned a[4][4], bf[4][2];
            #pragma unroll
            for (int i = 0; i < 4; i++) {
                int r = mw + 16 * i + g;
                uint2 x = *(const uint2*)&As[r * 36 + ks * 8 + 2 * tq];
                uint2 y = *(const uint2*)&As[(r + 8) * 36 + ks * 8 + 2 * tq];
                a[i][0] = x.x; a[i][1] = y.x; a[i][2] = x.y; a[i][3] = y.y;
            }
            #pragma unroll
            for (int j = 0; j < 4; j++) {
                int col = nw + 8 * j + g;
                bf[j][0] = Bs[(ks * 8 + 2 * tq) * 132 + col];
                bf[j][1] = Bs[(ks * 8 + 2 * tq + 1) * 132 + col];
            }
            #pragma unroll
            for (int i = 0; i < 4; i++)
                #pragma unroll
                for (int j = 0; j < 4; j++) mma8(c[i * 4 + j], a[i], bf[j]);
        }
        __syncthreads();
    }
    const int mode = g_mask_mode;
    const int* m32 = (const int*)mask;
    const unsigned char* m8 = (const unsigned char*)mask;
    const float* mf = (const float*)mask;
    #pragma unroll
    for (int i = 0; i < 4; i++) {
        int tl = mw + 16 * i + g;
        int rA = t0 + tl;
        #pragma unroll
        for (int j = 0; j < 4; j++) {
            int sl = nw + 8 * j + 2 * tq;
            int cs = s0 + sl;
            float* cc = c[i * 4 + j];
            size_t iA = ((size_t)bh * S + rA) * S + cs;
            size_t iB = iA + (size_t)8 * S;
            bool k0m, k1m, k2m, k3m;
            if (mode == 0) {
                int2 qa = *(const int2*)(m32 + iA); int2 qb = *(const int2*)(m32 + iB);
                k0m = qa.x != 0; k1m = qa.y != 0; k2m = qb.x != 0; k3m = qb.y != 0;
            } else if (mode == 1) {
                uchar2 qa = *(const uchar2*)(m8 + iA); uchar2 qb = *(const uchar2*)(m8 + iB);
                k0m = qa.x != 0; k1m = qa.y != 0; k2m = qb.x != 0; k3m = qb.y != 0;
            } else {
                float2 qa = *(const float2*)(mf + iA); float2 qb = *(const float2*)(mf + iB);
                k0m = qa.x != 0.0f; k1m = qa.y != 0.0f; k2m = qb.x != 0.0f; k3m = qb.y != 0.0f;
            }
            float p0 = k0m ? 0.0f : __expf(0.125f * cc[0]);
            float p1 = k1m ? 0.0f : __expf(0.125f * cc[1]);
            float p2 = k2m ? 0.0f : __expf(0.125f * cc[2]);
            float p3 = k3m ? 0.0f : __expf(0.125f * cc[3]);
            int cu = sl >> 1;
            su.Ps[tl * 68 + PSW(tl, cu)]           = __floats2half2_rn(p0, p1);
            su.Ps[(tl + 8) * 68 + PSW(tl + 8, cu)] = __floats2half2_rn(p2, p3);
        }
    }
    __syncthreads();
    if (tid < 128) {
        float rs = 0.f;
        const __half2* row = &su.Ps[tid * 68];
        #pragma unroll 16
        for (int j = 0; j < 64; j++) {
            float2 f = __half22float2(row[j]);
            rs += f.x + f.y;
        }
        cpc[((size_t)bh * 8 + blockIdx.x) * S + t0 + tid] = rs;
        int cu = tid >> 1, hh = tid & 1;
        float csum = 0.f;
        #pragma unroll 16
        for (int r = 0; r < 128; r++) {
            __half2 v = su.Ps[r * 68 + PSW(r, cu)];
            csum += __half2float(hh ? __high2half(v) : __low2half(v));
        }
        cpr[((size_t)bh * 8 + blockIdx.y) * S + s0 + tid] = csum;
    }
    __syncthreads();
    #pragma unroll
    for (int it = 0; it < 32; it++) {
        int t = it * 4 + (tid >> 6);
        int u = tid & 63;
        __half2 v = su.Ps[t * 68 + PSW(t, u)];
        *(__half2*)(P + ((size_t)bh * S + t0 + t) * S + s0 + 2 * u) = v;
    }
    #pragma unroll
    for (int it = 0; it < 32; it++) {
        int s = it * 4 + (tid >> 6);
        int tp = tid & 63;
        int cu = s >> 1, hh = s & 1;
        __half2 va = su.Ps[(2 * tp) * 68 + PSW(2 * tp, cu)];
        __half2 vb = su.Ps[(2 * tp + 1) * 68 + PSW(2 * tp + 1, cu)];
        __half h0 = hh ? __high2half(va) : __low2half(va);
        __half h1 = hh ? __high2half(vb) : __low2half(vb);
        *(__half2*)(PT + ((size_t)bh * S + s0 + s) * S + t0 + 2 * tp) = __halves2half2(h0, h1);
    }
}

// ---------------- reduce partials -> rinv, cinv ----------------
__global__ void rcinv_kernel(const float* __restrict__ cpr, const float* __restrict__ cpc,
                             float* __restrict__ rinv, float* __restrict__ cinv) {
    int bh = blockIdx.y;
    int x = blockIdx.x * 256 + threadIdx.x;
    float sr = 0.f, sc = 0.f;
    #pragma unroll
    for (int j = 0; j < 8; j++) {
        sr += cpr[((size_t)bh * 8 + j) * S + x];
        sc += cpc[((size_t)bh * 8 + j) * S + x];
    }
    rinv[bh * S + x] = 1.0f / sr;
    cinv[bh * S + x] = 1.0f / sc;
}

// ---------------- ctx fp16 HMMA 128x64 tiles, 8 warps (4m x 2n) ----------------
// C[m][d] = minv[m] * sum_k A[m][k] * XT[d][k]
__global__ void __launch_bounds__(256) ctxh_kernel(const __half* __restrict__ A,
                                                   const __half* __restrict__ XTh,
                                                   const float* __restrict__ minv,
                                                   float* __restrict__ C) {
    __shared__ unsigned Ah[128 * 20];  // [m][kword], 16 words + 4 pad
    __shared__ unsigned Bh[64 * 20];   // [d][kword]
    __shared__ float mv[128];
    const int bh = blockIdx.y, b = bh / H, h = bh % H;
    const int m0 = blockIdx.x * 128;
    const __half* Ag = A + ((size_t)bh * S + m0) * S;
    const __half* Bg = XTh + (size_t)bh * DK * S;
    const int tid = threadIdx.x, lane = tid & 31, w = tid >> 5;
    const int g = lane >> 2, tq = lane & 3;
    const int mw = (w & 3) * 32, nw = (w >> 2) * 32;
    if (tid < 128) mv[tid] = minv[bh * S + m0 + tid];
    const int arow = tid >> 1, ach = (tid & 1) * 2;   // 2 uint4 chunks per thread
    const int brow = tid >> 2, bch = tid & 3;
    float c[8][4] = {};
    for (int k0 = 0; k0 < S; k0 += 32) {
        {
            const __half* src = Ag + (size_t)arow * S + k0 + ach * 8;
            uint4 v0 = *(const uint4*)src;
            uint4 v1 = *(const uint4*)(src + 8);
            *(uint4*)&Ah[arow * 20 + ach * 4]       = v0;
            *(uint4*)&Ah[arow * 20 + (ach + 1) * 4] = v1;
        }
        {
            uint4 v = *(const uint4*)(Bg + (size_t)brow * S + k0 + bch * 8);
            *(uint4*)&Bh[brow * 20 + bch * 4] = v;
        }
        __syncthreads();
        #pragma unroll
        for (int ks = 0; ks < 2; ks++) {
            unsigned a[2][4], bf[4][2];
            #pragma unroll
            for (int i = 0; i < 2; i++) {
                int r = mw + 16 * i + g;
                a[i][0] = Ah[r * 20 + 8 * ks + tq];
                a[i][1] = Ah[(r + 8) * 20 + 8 * ks + tq];
                a[i][2] = Ah[r * 20 + 8 * ks + tq + 4];
                a[i][3] = Ah[(r + 8) * 20 + 8 * ks + tq + 4];
            }
            #pragma unroll
            for (int j = 0; j < 4; j++) {
                int col = nw + 8 * j + g;
                bf[j][0] = Bh[col * 20 + 8 * ks + tq];
                bf[j][1] = Bh[col * 20 + 8 * ks + tq + 4];
            }
            #pragma unroll
            for (int i = 0; i < 2; i++)
                #pragma unroll
                for (int j = 0; j < 4; j++) hmma16(c[i * 4 + j], a[i], bf[j]);
        }
        __syncthreads();
    }
    #pragma unroll
    for (int i = 0; i < 2; i++) {
        int rl = mw + 16 * i + g;
        float s0v = mv[rl], s1v = mv[rl + 8];
        #pragma unroll
        for (int j = 0; j < 4; j++) {
            int dcol = nw + 8 * j + 2 * tq;
            float* cc = c[i * 4 + j];
            size_t a0 = (size_t)(b * S + m0 + rl) * D + h * DK + dcol;
            *(float2*)(C + a0)                 = make_float2(cc[0] * s0v, cc[1] * s0v);
            *(float2*)(C + a0 + (size_t)8 * D) = make_float2(cc[2] * s1v, cc[3] * s1v);
        }
    }
}

// ---------------- batched LayerNorm over last dim (768) ----------------
__global__ void ln_kernel(const float* __restrict__ x,
                          const float* __restrict__ g1, const float* __restrict__ b1,
                          const float* __restrict__ g2, const float* __restrict__ b2,
                          float* __restrict__ out) {
    int row = blockIdx.x, tid = threadIdx.x;
    const float* gg = (row < Bz * S) ? g1 : g2;
    const float* bb = (row < Bz * S) ? b1 : b2;
    const float* xr = x + (size_t)row * D;
    float v0 = xr[tid], v1 = xr[tid + 256], v2 = xr[tid + 512];
    float s = v0 + v1 + v2;
    __shared__ float red[8];
    #pragma unroll
    for (int o = 16; o; o >>= 1) s += __shfl_xor_sync(0xffffffffu, s, o);
    if ((tid & 31) == 0) red[tid >> 5] = s;
    __syncthreads();
    float tot = 0.f;
    #pragma unroll
    for (int i = 0; i < 8; i++) tot += red[i];
    float mu = tot * (1.0f / 768.0f);
    float d0 = v0 - mu, d1 = v1 - mu, d2 = v2 - mu;
    float q = d0 * d0 + d1 * d1 + d2 * d2;
    #pragma unroll
    for (int o = 16; o; o >>= 1) q += __shfl_xor_sync(0xffffffffu, q, o);
    __syncthreads();
    if ((tid & 31) == 0) red[tid >> 5] = q;
    __syncthreads();
    float var = 0.f;
    #pragma unroll
    for (int i = 0; i < 8; i++) var += red[i];
    var *= (1.0f / 768.0f);
    float rs = rsqrtf(var + 1e-5f);
    float* orow = out + (size_t)row * D;
    orow[tid]       = d0 * rs * gg[tid]       + bb[tid];
    orow[tid + 256] = d1 * rs * gg[tid + 256] + bb[tid + 256];
    orow[tid + 512] = d2 * rs * gg[tid + 512] + bb[tid + 512];
}

// ---------------- launch ----------------
extern "C" void kernel_launch(void* const* d_in, const int* in_sizes, int n_in,
                              void* d_out, int out_size) {
    const float* pro1 = (const float*)d_in[0];
    const float* pro2 = (const float*)d_in[1];
    const void*  mask = d_in[2];
    const float* W_Q  = (const float*)d_in[3];
    const float* W_K  = (const float*)d_in[4];
    const float* fc1  = (const float*)d_in[5];
    const float* g1   = (const float*)d_in[6];
    const float* b1   = (const float*)d_in[7];
    const float* g2   = (const float*)d_in[8];
    const float* b2   = (const float*)d_in[9];
    float* out = (float*)d_out;

    float *Qp, *Kp, *QTp, *KTf, *CX, *Tp, *CPR, *CPC, *RI, *CI;
    __half *QTh, *KTh, *Pp, *PTp;
    cudaGetSymbolAddress((void**)&Qp, g_Q);
    cudaGetSymbolAddress((void**)&Kp, g_K);
    cudaGetSymbolAddress((void**)&QTp, g_QT);
    cudaGetSymbolAddress((void**)&QTh, g_QTh);
    cudaGetSymbolAddress((void**)&KTh, g_KTh);
    cudaGetSymbolAddress((void**)&KTf, g_KTf);
    cudaGetSymbolAddress((void**)&Pp, g_P);
    cudaGetSymbolAddress((void**)&PTp, g_PT);
    cudaGetSymbolAddress((void**)&CX, g_ctx);
    cudaGetSymbolAddress((void**)&Tp, g_t);
    cudaGetSymbolAddress((void**)&CPR, g_cpr);
    cudaGetSymbolAddress((void**)&CPC, g_cpc);
    cudaGetSymbolAddress((void**)&RI, g_rinv);
    cudaGetSymbolAddress((void**)&CI, g_cinv);

    detect_mask_kernel<<<1, 256>>>((const unsigned int*)mask);

    dim3 gProj(12, 32);   // n-tiles 768/64, m-tiles 4096/128
    mm128_kernel<<<gProj, 256>>>(pro1, W_Q, Qp, 1);
    mm128_kernel<<<gProj, 256>>>(pro2, W_K, Kp, 1);

    tr_kernel<<<dim3(32, 2, BH), dim3(32, 8)>>>(Qp, QTp, QTh);
    tr_kernel<<<dim3(32, 2, BH), dim3(32, 8)>>>(Kp, KTf, KTh);

    scoresT_kernel<<<dim3(8, 8, BH), 256>>>(Kp, QTp, mask, Pp, PTp, CPR, CPC);

    rcinv_kernel<<<dim3(4, BH), 256>>>(CPR, CPC, RI, CI);

    ctxh_kernel<<<dim3(8, BH), 256>>>(PTp, KTh, RI, CX);                      // ctx1
    ctxh_kernel<<<dim3(8, BH), 256>>>(Pp, QTh, CI, CX + (size_t)Bz * S * D);  // ctx2

    mm128_kernel<<<dim3(12, 64), 256>>>(CX, fc1, Tp, 0);

    ln_kernel<<<2 * Bz * S, 256>>>(Tp, g1, b1, g2, b2, out);
}